// round 5
// baseline (speedup 1.0000x reference)
#include <cuda_runtime.h>
#include <math.h>
#include <stdint.h>

// Problem constants
#define BB      4
#define TT      2048
#define HID     1024
#define NH      8
#define HD      128
#define KS      4
#define INTER   2816
#define MROWS   (BB * TT)            // 8192
#define NCHUNK  16                   // T / 128
#define CLEN    128

// ---------------- scratch (single __device__ array, offsets in floats) ----
static const size_t SZ_MH = (size_t)MROWS * HID;      // 8388608
static const size_t SZ_MI = (size_t)MROWS * INTER;    // 23068672

static const size_t OFF_H     = 0;
static const size_t OFF_QKV   = OFF_H     + SZ_MH;
static const size_t OFF_CONV  = OFF_QKV   + 3 * SZ_MH;
static const size_t OFF_LOCAL = OFF_CONV  + SZ_MH;
static const size_t OFF_RKS   = OFF_LOCAL + SZ_MH;
static const size_t OFF_RKV   = OFF_RKS   + SZ_MH;
static const size_t OFF_O     = OFF_RKV   + SZ_MH;
static const size_t OFF_TMP   = OFF_O     + SZ_MH;
static const size_t OFF_O2    = OFF_TMP   + SZ_MH;
static const size_t OFF_ATTN  = OFF_O2    + SZ_MH;
static const size_t OFF_X1    = OFF_ATTN  + SZ_MH;
static const size_t OFF_H2    = OFF_X1    + SZ_MH;
static const size_t OFF_FFA   = OFF_H2    + SZ_MH;
static const size_t OFF_FFB   = OFF_FFA   + SZ_MI;
static const size_t OFF_FFN   = OFF_FFB   + SZ_MI;
static const size_t OFF_CKS   = OFF_FFN   + SZ_MH;
static const size_t OFF_CKV   = OFF_CKS   + 65536;
static const size_t OFF_PKS   = OFF_CKV   + 65536;
static const size_t OFF_PKV   = OFF_PKS   + 65536;
// tf32-rounded weight copies
static const size_t OFF_WQKV  = OFF_PKV   + 65536;
static const size_t OFF_WOP   = OFF_WQKV  + 3 * (size_t)HID * HID;
static const size_t OFF_WOG   = OFF_WOP   + (size_t)HID * HID;
static const size_t OFF_WPW   = OFF_WOG   + (size_t)HID * HID;
static const size_t OFF_WGT   = OFF_WPW   + (size_t)HID * HID;
static const size_t OFF_WW1   = OFF_WGT   + 2 * (size_t)HID * HID;
static const size_t OFF_WW2   = OFF_WW1   + (size_t)INTER * HID;
static const size_t OFF_WW3   = OFF_WW2   + (size_t)INTER * HID;
static const size_t SCRATCH_FLOATS = OFF_WW3 + (size_t)INTER * HID;

__device__ float g_scratch[SCRATCH_FLOATS];

// ---------------- helpers ----------------
__device__ __forceinline__ float sigmoidf_(float x) { return 1.0f / (1.0f + expf(-x)); }
__device__ __forceinline__ float siluf_(float x)    { return x / (1.0f + expf(-x)); }

__device__ __forceinline__ unsigned f2tf(float f) {
    unsigned u; asm("cvt.rna.tf32.f32 %0, %1;" : "=r"(u) : "f"(f)); return u;
}
__device__ __forceinline__ float tf32r(float f) { return __uint_as_float(f2tf(f)); }

__device__ __forceinline__ void mma_tf32(float* c, const unsigned* a, const unsigned* b) {
    asm volatile("mma.sync.aligned.m16n8k8.row.col.f32.tf32.tf32.f32 "
        "{%0,%1,%2,%3}, {%4,%5,%6,%7}, {%8,%9}, {%0,%1,%2,%3};"
        : "+f"(c[0]), "+f"(c[1]), "+f"(c[2]), "+f"(c[3])
        : "r"(a[0]), "r"(a[1]), "r"(a[2]), "r"(a[3]), "r"(b[0]), "r"(b[1]));
}

// ---------------- weight tf32 rounding ------------------------------------
__global__ void cvt_tf32_kernel(const float* __restrict__ s, float* __restrict__ d, int n) {
    int i = blockIdx.x * blockDim.x + threadIdx.x;
    if (i < n) d[i] = tf32r(s[i]);
}

// ---------------- rmsnorm (tf32-rounded output) ---------------------------
__global__ void rmsnorm_kernel(const float* __restrict__ x, const float* __restrict__ w,
                               float* __restrict__ o) {
    int row = blockIdx.x;
    size_t base = (size_t)row * HID;
    float4 v = ((const float4*)(x + base))[threadIdx.x];
    float ss = v.x * v.x + v.y * v.y + v.z * v.z + v.w * v.w;
    __shared__ float sred[8];
    int lane = threadIdx.x & 31, wid = threadIdx.x >> 5;
    #pragma unroll
    for (int k = 16; k; k >>= 1) ss += __shfl_xor_sync(0xFFFFFFFFu, ss, k);
    if (lane == 0) sred[wid] = ss;
    __syncthreads();
    if (wid == 0) {
        float t = (lane < 8) ? sred[lane] : 0.0f;
        #pragma unroll
        for (int k = 4; k; k >>= 1) t += __shfl_xor_sync(0xFFFFFFFFu, t, k);
        if (lane == 0) sred[0] = t;
    }
    __syncthreads();
    float scale = rsqrtf(sred[0] * (1.0f / (float)HID) + 1e-6f);
    float4 wv = ((const float4*)w)[threadIdx.x];
    float4 r = make_float4(tf32r(v.x * scale * wv.x), tf32r(v.y * scale * wv.y),
                           tf32r(v.z * scale * wv.z), tf32r(v.w * scale * wv.w));
    ((float4*)(o + base))[threadIdx.x] = r;
}

// ---------------- TF32 tensor-core GEMM, 64x64 warp tiles ------------------
// C[M,N](ldC) = A[M,K](ldA) @ W[N,K](ldW)^T. Inputs pre-rounded to tf32.
// CTA tile 128x256, K-tile 32, 8 warps (2x4), each warp 64x64 via 4x8
// m16n8k8 tiles. Double-buffered cp.async. SPITCH=36 keeps fragment LDS
// conflict-free. 1 CTA/SM (smem ~108KB).
#define SPITCH  36
#define ABUF    (128 * SPITCH)          // A stage floats
#define BBUF    (256 * SPITCH)          // B stage floats
#define STG     (ABUF + BBUF)           // 13824 floats per stage
#define TGEMM_SMEM (2 * STG * sizeof(float))   // 110592 bytes

__device__ __forceinline__ void tile_load_a(float* s, const float* g, int ld, int k0, int tid) {
    #pragma unroll
    for (int i = 0; i < 4; i++) {
        int idx = tid + i * 256;               // 0..1023
        int row = idx >> 3;
        int c4  = (idx & 7) * 4;
        unsigned saddr = (unsigned)__cvta_generic_to_shared(s + row * SPITCH + c4);
        const float* gp = g + (size_t)row * ld + k0 + c4;
        asm volatile("cp.async.cg.shared.global [%0], [%1], 16;" :: "r"(saddr), "l"(gp));
    }
}
__device__ __forceinline__ void tile_load_b(float* s, const float* g, int ld, int k0, int tid) {
    #pragma unroll
    for (int i = 0; i < 8; i++) {
        int idx = tid + i * 256;               // 0..2047
        int row = idx >> 3;
        int c4  = (idx & 7) * 4;
        unsigned saddr = (unsigned)__cvta_generic_to_shared(s + row * SPITCH + c4);
        const float* gp = g + (size_t)row * ld + k0 + c4;
        asm volatile("cp.async.cg.shared.global [%0], [%1], 16;" :: "r"(saddr), "l"(gp));
    }
}

template <bool ACC, bool ROUND>
__global__ __launch_bounds__(256, 1)
void tgemm_kernel(const float* __restrict__ A, int ldA,
                  const float* __restrict__ W, int ldW,
                  float* __restrict__ C, int ldC, int K) {
    extern __shared__ float smem[];
    int tid = threadIdx.x;
    int wid = tid >> 5, lane = tid & 31;
    int warp_m = wid & 1, warp_n = wid >> 1;         // 2 x 4 warp grid
    int m0 = blockIdx.y * 128, n0 = blockIdx.x * 256;
    const float* Ag = A + (size_t)m0 * ldA;
    const float* Wg = W + (size_t)n0 * ldW;
    int qr = lane >> 2, qc = lane & 3;

    float acc[4][8][4];
    #pragma unroll
    for (int mt = 0; mt < 4; mt++)
        #pragma unroll
        for (int nt = 0; nt < 8; nt++)
            #pragma unroll
            for (int i = 0; i < 4; i++) acc[mt][nt][i] = 0.0f;

    int KT = K / 32;
    tile_load_a(smem, Ag, ldA, 0, tid);
    tile_load_b(smem + ABUF, Wg, ldW, 0, tid);
    asm volatile("cp.async.commit_group;");

    for (int kt = 0; kt < KT; kt++) {
        int cur = kt & 1;
        if (kt + 1 < KT) {
            float* nx = smem + (cur ^ 1) * STG;
            tile_load_a(nx, Ag, ldA, (kt + 1) * 32, tid);
            tile_load_b(nx + ABUF, Wg, ldW, (kt + 1) * 32, tid);
            asm volatile("cp.async.commit_group;");
            asm volatile("cp.async.wait_group 1;");
        } else {
            asm volatile("cp.async.wait_group 0;");
        }
        __syncthreads();
        const unsigned* Ab = (const unsigned*)(smem + cur * STG);
        const unsigned* Wb = (const unsigned*)(smem + cur * STG + ABUF);
        #pragma unroll
        for (int ks = 0; ks < 4; ks++) {
            int k0 = ks * 8;
            unsigned af[4][4];
            #pragma unroll
            for (int mt = 0; mt < 4; mt++) {
                int r = warp_m * 64 + mt * 16 + qr;
                af[mt][0] = Ab[r * SPITCH + k0 + qc];
                af[mt][1] = Ab[(r + 8) * SPITCH + k0 + qc];
                af[mt][2] = Ab[r * SPITCH + k0 + qc + 4];
                af[mt][3] = Ab[(r + 8) * SPITCH + k0 + qc + 4];
            }
            #pragma unroll
            for (int nt = 0; nt < 8; nt++) {
                unsigned bf[2];
                int cc = warp_n * 64 + nt * 8 + qr;
                bf[0] = Wb[cc * SPITCH + k0 + qc];
                bf[1] = Wb[cc * SPITCH + k0 + qc + 4];
                #pragma unroll
                for (int mt = 0; mt < 4; mt++)
                    mma_tf32(acc[mt][nt], af[mt], bf);
            }
        }
        __syncthreads();
    }

    #pragma unroll
    for (int mt = 0; mt < 4; mt++)
        #pragma unroll
        for (int nt = 0; nt < 8; nt++) {
            int row = m0 + warp_m * 64 + mt * 16 + qr;
            int col = n0 + warp_n * 64 + nt * 8 + qc * 2;
            float* p0 = C + (size_t)row * ldC + col;
            float* p1 = C + (size_t)(row + 8) * ldC + col;
            float2 r0 = make_float2(acc[mt][nt][0], acc[mt][nt][1]);
            float2 r1 = make_float2(acc[mt][nt][2], acc[mt][nt][3]);
            if (ROUND) {
                r0.x = tf32r(r0.x); r0.y = tf32r(r0.y);
                r1.x = tf32r(r1.x); r1.y = tf32r(r1.y);
            }
            if (ACC) {
                float2 o0 = *(float2*)p0, o1 = *(float2*)p1;
                r0.x += o0.x; r0.y += o0.y; r1.x += o1.x; r1.y += o1.y;
            }
            *(float2*)p0 = r0;
            *(float2*)p1 = r1;
        }
}

// ---------------- depthwise causal conv (KS=4) + bias + silu --------------
__global__ void conv_silu_kernel(const float* __restrict__ h, const float* __restrict__ cw,
                                 const float* __restrict__ cb, float* __restrict__ o) {
    size_t idx = (size_t)blockIdx.x * blockDim.x + threadIdx.x;
    int c = idx & (HID - 1);
    int t = (int)((idx >> 10) & (TT - 1));
    int b = (int)(idx >> 21);
    float acc = cb[c];
    #pragma unroll
    for (int j = 0; j < KS; j++) {
        int tt = t + j - (KS - 1);
        if (tt >= 0) acc += h[((size_t)(b * TT + tt)) * HID + c] * cw[c * KS + j];
    }
    o[idx] = tf32r(siluf_(acc));
}

// ---------------- elu(x)+1 applied in place to q,k cols of qkv ------------
__global__ void eluqk_kernel(float* __restrict__ qkv) {
    size_t idx = (size_t)blockIdx.x * blockDim.x + threadIdx.x;
    size_t row = idx >> 11;
    int col = (int)(idx & 2047);
    float* p = qkv + row * 3072 + col;
    float v = *p;
    *p = (v > 0.0f) ? (v + 1.0f) : expf(v);
}

// ---------------- scan pass A ---------------------------------------------
__global__ void scan_chunk_kernel(const float* __restrict__ qkv, const float* __restrict__ dp,
                                  float* __restrict__ rks, float* __restrict__ rkv,
                                  float* __restrict__ cks, float* __restrict__ ckv) {
    int c = blockIdx.x * blockDim.x + threadIdx.x;
    int j = blockIdx.y;
    int b = blockIdx.z;
    float d = sigmoidf_(dp[c >> 7]);
    float sks = 0.0f, skv = 0.0f;
    size_t base  = ((size_t)(b * TT + j * CLEN)) * 3072 + c;
    size_t obase = ((size_t)(b * TT + j * CLEN)) * HID + c;
    for (int i = 0; i < CLEN; i++) {
        float kk = qkv[base + 1024];
        float vv = qkv[base + 2048];
        sks = d * sks + kk;
        skv = d * skv + kk * vv;
        rks[obase] = sks;
        rkv[obase] = skv;
        base += 3072; obase += HID;
    }
    cks[(b * NCHUNK + j) * HID + c] = sks;
    ckv[(b * NCHUNK + j) * HID + c] = skv;
}

// ---------------- scan pass B ---------------------------------------------
__global__ void scan_carry_kernel(const float* __restrict__ dp,
                                  const float* __restrict__ cks, const float* __restrict__ ckv,
                                  float* __restrict__ pks, float* __restrict__ pkv) {
    int c = blockIdx.x * blockDim.x + threadIdx.x;
    int b = blockIdx.y;
    float d = sigmoidf_(dp[c >> 7]);
    float dC = expf((float)CLEN * logf(d));
    float sks = 0.0f, skv = 0.0f;
    for (int j = 0; j < NCHUNK; j++) {
        int idx = (b * NCHUNK + j) * HID + c;
        pks[idx] = sks;
        pkv[idx] = skv;
        sks = dC * sks + cks[idx];
        skv = dC * skv + ckv[idx];
    }
}

// ---------------- scan pass C ---------------------------------------------
__global__ void scan_fix_kernel(const float* __restrict__ dp,
                                const float* __restrict__ pks, const float* __restrict__ pkv,
                                float* __restrict__ rks, float* __restrict__ rkv) {
    size_t idx = (size_t)blockIdx.x * blockDim.x + threadIdx.x;
    int c = (int)(idx & (HID - 1));
    int t = (int)((idx >> 10) & (TT - 1));
    int b = (int)(idx >> 21);
    int i = t & (CLEN - 1);
    int j = t >> 7;
    float d = sigmoidf_(dp[c >> 7]);
    float pw = expf((float)(i + 1) * logf(d));
    int pidx = (b * NCHUNK + j) * HID + c;
    rks[idx] += pks[pidx] * pw;
    rkv[idx] += pkv[pidx] * pw;
}

// ---------------- den + o (tf32-rounded output) ---------------------------
__global__ void attn_o_kernel(const float* __restrict__ qkv,
                              const float* __restrict__ rks, const float* __restrict__ rkv,
                              float* __restrict__ o) {
    int gw = (blockIdx.x * blockDim.x + threadIdx.x) >> 5;
    int lane = threadIdx.x & 31;
    int row = gw >> 3;
    int hh = gw & 7;
    size_t qbase = (size_t)row * 3072 + hh * HD;
    size_t rbase = (size_t)row * HID  + hh * HD;
    float qv[4], s = 0.0f;
    #pragma unroll
    for (int u = 0; u < 4; u++) {
        int dpos = lane + u * 32;
        qv[u] = qkv[qbase + dpos];
        s += qv[u] * rks[rbase + dpos];
    }
    #pragma unroll
    for (int k = 16; k; k >>= 1) s += __shfl_xor_sync(0xFFFFFFFFu, s, k);
    float inv = 1.0f / fmaxf(s, 1e-6f);
    #pragma unroll
    for (int u = 0; u < 4; u++) {
        int dpos = lane + u * 32;
        o[rbase + dpos] = tf32r(qv[u] * rkv[rbase + dpos] * inv);
    }
}

// ---------------- out-gate mix (tf32-rounded output) ----------------------
__global__ void outgate_mix_kernel(const float* __restrict__ glin, const float* __restrict__ gb,
                                   const float* __restrict__ o, const float* __restrict__ qkv,
                                   float* __restrict__ o2) {
    size_t idx = (size_t)blockIdx.x * blockDim.x + threadIdx.x;
    int c = (int)(idx & (HID - 1));
    size_t row = idx >> 10;
    float g = sigmoidf_(glin[idx] + gb[c]);
    float v = qkv[row * 3072 + 2048 + c];
    o2[idx] = tf32r(g * o[idx] + (1.0f - g) * v);
}

// ---------------- gate-mix residual ---------------------------------------
__global__ void gmix_residual_kernel(const float* __restrict__ x, const float* __restrict__ glin,
                                     const float* __restrict__ local, const float* __restrict__ attn,
                                     float* __restrict__ x1) {
    size_t idx = (size_t)blockIdx.x * blockDim.x + threadIdx.x;
    float s = sigmoidf_(glin[idx]);
    x1[idx] = x[idx] + s * local[idx] + (1.0f - s) * attn[idx];
}

// ---------------- swiglu (tf32-rounded output) ----------------------------
__global__ void swiglu_kernel(float* __restrict__ a, const float* __restrict__ b) {
    size_t idx = (size_t)blockIdx.x * blockDim.x + threadIdx.x;
    a[idx] = tf32r(siluf_(a[idx]) * b[idx]);
}

// ---------------- final residual ------------------------------------------
__global__ void add_kernel(const float* __restrict__ a, const float* __restrict__ b,
                           float* __restrict__ o) {
    size_t idx = (size_t)blockIdx.x * blockDim.x + threadIdx.x;
    o[idx] = a[idx] + b[idx];
}

// ---------------- host side ------------------------------------------------
static inline void run_gemm(const float* A, int ldA, const float* W, int ldW,
                            float* C, int ldC, int M, int N, int K, bool acc, bool rnd) {
    dim3 grid(N / 256, M / 128);
    if (acc)      tgemm_kernel<true,  false><<<grid, 256, TGEMM_SMEM>>>(A, ldA, W, ldW, C, ldC, K);
    else if (rnd) tgemm_kernel<false, true ><<<grid, 256, TGEMM_SMEM>>>(A, ldA, W, ldW, C, ldC, K);
    else          tgemm_kernel<false, false><<<grid, 256, TGEMM_SMEM>>>(A, ldA, W, ldW, C, ldC, K);
}

extern "C" void kernel_launch(void* const* d_in, const int* in_sizes, int n_in,
                              void* d_out, int out_size) {
    const float* x           = (const float*)d_in[0];
    const float* qkv_w       = (const float*)d_in[1];
    const float* out_proj_w  = (const float*)d_in[2];
    const float* out_gate_w  = (const float*)d_in[3];
    const float* out_gate_b  = (const float*)d_in[4];
    const float* decay_param = (const float*)d_in[5];
    const float* conv_w      = (const float*)d_in[6];
    const float* conv_b      = (const float*)d_in[7];
    const float* pw_w        = (const float*)d_in[8];
    const float* gate_w      = (const float*)d_in[9];
    const float* w1          = (const float*)d_in[10];
    const float* w2          = (const float*)d_in[11];
    const float* w3          = (const float*)d_in[12];
    const float* norm1_w     = (const float*)d_in[13];
    const float* norm2_w     = (const float*)d_in[14];
    float* out = (float*)d_out;

    static int smem_set = 0;
    if (!smem_set) {
        cudaFuncSetAttribute(tgemm_kernel<false, false>,
                             cudaFuncAttributeMaxDynamicSharedMemorySize, (int)TGEMM_SMEM);
        cudaFuncSetAttribute(tgemm_kernel<false, true>,
                             cudaFuncAttributeMaxDynamicSharedMemorySize, (int)TGEMM_SMEM);
        cudaFuncSetAttribute(tgemm_kernel<true, false>,
                             cudaFuncAttributeMaxDynamicSharedMemorySize, (int)TGEMM_SMEM);
        smem_set = 1;
    }

    float* S = nullptr;
    cudaGetSymbolAddress((void**)&S, g_scratch);

    float* g_h    = S + OFF_H;
    float* g_qkv  = S + OFF_QKV;
    float* g_conv = S + OFF_CONV;
    float* g_loc  = S + OFF_LOCAL;
    float* g_rks  = S + OFF_RKS;
    float* g_rkv  = S + OFF_RKV;
    float* g_o    = S + OFF_O;
    float* g_tmp  = S + OFF_TMP;
    float* g_o2   = S + OFF_O2;
    float* g_attn = S + OFF_ATTN;
    float* g_x1   = S + OFF_X1;
    float* g_h2   = S + OFF_H2;
    float* g_ffa  = S + OFF_FFA;
    float* g_ffb  = S + OFF_FFB;
    float* g_ffn  = S + OFF_FFN;
    float* g_cks  = S + OFF_CKS;
    float* g_ckv  = S + OFF_CKV;
    float* g_pks  = S + OFF_PKS;
    float* g_pkv  = S + OFF_PKV;
    float* c_qkvw = S + OFF_WQKV;
    float* c_opw  = S + OFF_WOP;
    float* c_ogw  = S + OFF_WOG;
    float* c_pww  = S + OFF_WPW;
    float* c_gtw  = S + OFF_WGT;
    float* c_w1   = S + OFF_WW1;
    float* c_w2   = S + OFF_WW2;
    float* c_w3   = S + OFF_WW3;

    const int NEH = 256;
    const int GMH = (int)(SZ_MH / NEH);
    const int GMI = (int)(SZ_MI / NEH);

    // 0. round weights to tf32 once per launch
    cvt_tf32_kernel<<<(3 * HID * HID) / 256, 256>>>(qkv_w, c_qkvw, 3 * HID * HID);
    cvt_tf32_kernel<<<(HID * HID) / 256, 256>>>(out_proj_w, c_opw, HID * HID);
    cvt_tf32_kernel<<<(HID * HID) / 256, 256>>>(out_gate_w, c_ogw, HID * HID);
    cvt_tf32_kernel<<<(HID * HID) / 256, 256>>>(pw_w, c_pww, HID * HID);
    cvt_tf32_kernel<<<(2 * HID * HID) / 256, 256>>>(gate_w, c_gtw, 2 * HID * HID);
    cvt_tf32_kernel<<<(INTER * HID) / 256, 256>>>(w1, c_w1, INTER * HID);
    cvt_tf32_kernel<<<(INTER * HID) / 256, 256>>>(w2, c_w2, INTER * HID);
    cvt_tf32_kernel<<<(INTER * HID) / 256, 256>>>(w3, c_w3, INTER * HID);

    // 1. h = rmsnorm(x, norm1_w)
    rmsnorm_kernel<<<MROWS, 256>>>(x, norm1_w, g_h);

    // 2. qkv = h @ qkv_w^T
    run_gemm(g_h, HID, c_qkvw, HID, g_qkv, 3 * HID, MROWS, 3 * HID, HID, false, false);

    // 3. conv branch
    conv_silu_kernel<<<GMH, NEH>>>(g_h, conv_w, conv_b, g_conv);
    run_gemm(g_conv, HID, c_pww, HID, g_loc, HID, MROWS, HID, HID, false, true);

    // 4. elu+1 on q,k
    eluqk_kernel<<<(int)((size_t)MROWS * 2048 / NEH), NEH>>>(g_qkv);

    // 5. decayed scans
    {
        dim3 gA(HID / 256, NCHUNK, BB);
        scan_chunk_kernel<<<gA, 256>>>(g_qkv, decay_param, g_rks, g_rkv, g_cks, g_ckv);
        dim3 gB(HID / 256, BB);
        scan_carry_kernel<<<gB, 256>>>(decay_param, g_cks, g_ckv, g_pks, g_pkv);
        scan_fix_kernel<<<GMH, NEH>>>(decay_param, g_pks, g_pkv, g_rks, g_rkv);
    }

    // 6. o
    attn_o_kernel<<<MROWS * NH * 32 / 256, 256>>>(g_qkv, g_rks, g_rkv, g_o);

    // 7. out gate
    run_gemm(g_o, HID, c_ogw, HID, g_tmp, HID, MROWS, HID, HID, false, false);
    outgate_mix_kernel<<<GMH, NEH>>>(g_tmp, out_gate_b, g_o, g_qkv, g_o2);

    // 8. attn = o2 @ out_proj^T
    run_gemm(g_o2, HID, c_opw, HID, g_attn, HID, MROWS, HID, HID, false, true);

    // 9. gmix (split-K over concat)
    run_gemm(g_loc,  HID, c_gtw,       2 * HID, g_tmp, HID, MROWS, HID, HID, false, false);
    run_gemm(g_attn, HID, c_gtw + HID, 2 * HID, g_tmp, HID, MROWS, HID, HID, true, false);
    gmix_residual_kernel<<<GMH, NEH>>>(x, g_tmp, g_loc, g_attn, g_x1);

    // 10. FFN
    rmsnorm_kernel<<<MROWS, 256>>>(g_x1, norm2_w, g_h2);
    run_gemm(g_h2, HID, c_w1, HID, g_ffa, INTER, MROWS, INTER, HID, false, false);
    run_gemm(g_h2, HID, c_w2, HID, g_ffb, INTER, MROWS, INTER, HID, false, false);
    swiglu_kernel<<<GMI, NEH>>>(g_ffa, g_ffb);
    run_gemm(g_ffa, INTER, c_w3, INTER, g_ffn, HID, MROWS, HID, INTER, false, false);

    // 11. out = x1 + ffn
    add_kernel<<<GMH, NEH>>>(g_x1, g_ffn, out);
}

// round 6
// speedup vs baseline: 1.1242x; 1.1242x over previous
#include <cuda_runtime.h>
#include <math.h>
#include <stdint.h>

// Problem constants
#define BB      4
#define TT      2048
#define HID     1024
#define NH      8
#define HD      128
#define KS      4
#define INTER   2816
#define MROWS   (BB * TT)            // 8192
#define NCHUNK  16                   // T / 128
#define CLEN    128

// ---------------- scratch ----------------
static const size_t SZ_MH = (size_t)MROWS * HID;      // 8388608
static const size_t SZ_MI = (size_t)MROWS * INTER;    // 23068672

static const size_t OFF_H     = 0;
static const size_t OFF_QKV   = OFF_H     + SZ_MH;
static const size_t OFF_CONV  = OFF_QKV   + 3 * SZ_MH;
static const size_t OFF_LOCAL = OFF_CONV  + SZ_MH;
static const size_t OFF_RKS   = OFF_LOCAL + SZ_MH;
static const size_t OFF_RKV   = OFF_RKS   + SZ_MH;
static const size_t OFF_O     = OFF_RKV   + SZ_MH;
static const size_t OFF_TMP   = OFF_O     + SZ_MH;
static const size_t OFF_O2    = OFF_TMP   + SZ_MH;
static const size_t OFF_ATTN  = OFF_O2    + SZ_MH;
static const size_t OFF_X1    = OFF_ATTN  + SZ_MH;
static const size_t OFF_H2    = OFF_X1    + SZ_MH;
static const size_t OFF_FF    = OFF_H2    + SZ_MH;            // [M, 2*INTER]
static const size_t OFF_FFA   = OFF_FF    + 2 * SZ_MI;        // [M, INTER]
static const size_t OFF_CKS   = OFF_FFA   + SZ_MI;
static const size_t OFF_CKV   = OFF_CKS   + 65536;
static const size_t OFF_PKS   = OFF_CKV   + 65536;
static const size_t OFF_PKV   = OFF_PKS   + 65536;
// tf32-rounded weight copies (w1 and w2 MUST be adjacent for the fused GEMM)
static const size_t OFF_WQKV  = OFF_PKV   + 65536;
static const size_t OFF_WOP   = OFF_WQKV  + 3 * (size_t)HID * HID;
static const size_t OFF_WOG   = OFF_WOP   + (size_t)HID * HID;
static const size_t OFF_WPW   = OFF_WOG   + (size_t)HID * HID;
static const size_t OFF_WGT   = OFF_WPW   + (size_t)HID * HID;
static const size_t OFF_WW1   = OFF_WGT   + 2 * (size_t)HID * HID;
static const size_t OFF_WW2   = OFF_WW1   + (size_t)INTER * HID;   // adjacent to WW1
static const size_t OFF_WW3   = OFF_WW2   + (size_t)INTER * HID;
static const size_t SCRATCH_FLOATS = OFF_WW3 + (size_t)INTER * HID;

__device__ float g_scratch[SCRATCH_FLOATS];

// ---------------- helpers ----------------
__device__ __forceinline__ float sigmoidf_(float x) { return 1.0f / (1.0f + expf(-x)); }
__device__ __forceinline__ float siluf_(float x)    { return x / (1.0f + expf(-x)); }
__device__ __forceinline__ float elup1_(float x)    { return (x > 0.0f) ? (x + 1.0f) : expf(x); }

__device__ __forceinline__ unsigned f2tf(float f) {
    unsigned u; asm("cvt.rna.tf32.f32 %0, %1;" : "=r"(u) : "f"(f)); return u;
}
__device__ __forceinline__ float tf32r(float f) { return __uint_as_float(f2tf(f)); }

__device__ __forceinline__ void mma_tf32(float* c, const unsigned* a, const unsigned* b) {
    asm volatile("mma.sync.aligned.m16n8k8.row.col.f32.tf32.tf32.f32 "
        "{%0,%1,%2,%3}, {%4,%5,%6,%7}, {%8,%9}, {%0,%1,%2,%3};"
        : "+f"(c[0]), "+f"(c[1]), "+f"(c[2]), "+f"(c[3])
        : "r"(a[0]), "r"(a[1]), "r"(a[2]), "r"(a[3]), "r"(b[0]), "r"(b[1]));
}

// ---------------- weight tf32 rounding ------------------------------------
__global__ void cvt_tf32_kernel(const float* __restrict__ s, float* __restrict__ d, int n) {
    int i = blockIdx.x * blockDim.x + threadIdx.x;
    if (i < n) d[i] = tf32r(s[i]);
}

// ---------------- rmsnorm (tf32-rounded output) ---------------------------
__global__ void rmsnorm_kernel(const float* __restrict__ x, const float* __restrict__ w,
                               float* __restrict__ o) {
    int row = blockIdx.x;
    size_t base = (size_t)row * HID;
    float4 v = ((const float4*)(x + base))[threadIdx.x];
    float ss = v.x * v.x + v.y * v.y + v.z * v.z + v.w * v.w;
    __shared__ float sred[8];
    int lane = threadIdx.x & 31, wid = threadIdx.x >> 5;
    #pragma unroll
    for (int k = 16; k; k >>= 1) ss += __shfl_xor_sync(0xFFFFFFFFu, ss, k);
    if (lane == 0) sred[wid] = ss;
    __syncthreads();
    if (wid == 0) {
        float t = (lane < 8) ? sred[lane] : 0.0f;
        #pragma unroll
        for (int k = 4; k; k >>= 1) t += __shfl_xor_sync(0xFFFFFFFFu, t, k);
        if (lane == 0) sred[0] = t;
    }
    __syncthreads();
    float scale = rsqrtf(sred[0] * (1.0f / (float)HID) + 1e-6f);
    float4 wv = ((const float4*)w)[threadIdx.x];
    float4 r = make_float4(tf32r(v.x * scale * wv.x), tf32r(v.y * scale * wv.y),
                           tf32r(v.z * scale * wv.z), tf32r(v.w * scale * wv.w));
    ((float4*)(o + base))[threadIdx.x] = r;
}

// ---------------- TF32 tensor-core GEMM (R4 config + epilogue modes) -------
// C[M,N](ldC) = A[M,K](ldA) @ W[N,K](ldW)^T. Inputs pre-rounded to tf32.
// 128x128x32 CTA tile, 8 warps, warp 64x32 via 4x4 m16n8k8. 2 CTAs/SM.
// EPI: 0 = store (ROUND optional), 1 = accumulate into C, 2 = out-gate mix:
//      g = sigmoid(acc + gb[col]); C = tf32r(g*oin[row,col] + (1-g)*v[row,col])
#define SPITCH 36
#define SBUF   (128 * SPITCH)
#define TGEMM_SMEM (4 * SBUF * sizeof(float))   // 73728 bytes

__device__ __forceinline__ void tile_load(float* s, const float* g, int ld, int k0, int tid) {
    #pragma unroll
    for (int i = 0; i < 4; i++) {
        int idx = tid + i * 256;
        int row = idx >> 3;
        int c4  = (idx & 7) * 4;
        unsigned saddr = (unsigned)__cvta_generic_to_shared(s + row * SPITCH + c4);
        const float* gp = g + (size_t)row * ld + k0 + c4;
        asm volatile("cp.async.cg.shared.global [%0], [%1], 16;" :: "r"(saddr), "l"(gp));
    }
}

template <int EPI, bool ROUND>
__global__ __launch_bounds__(256, 2)
void tgemm_kernel(const float* __restrict__ A, int ldA,
                  const float* __restrict__ W, int ldW,
                  float* __restrict__ C, int ldC, int K,
                  const float* __restrict__ gb,
                  const float* __restrict__ oin,
                  const float* __restrict__ qkvp) {
    extern __shared__ float smem[];
    float* AsB = smem;
    float* WsB = smem + 2 * SBUF;
    int tid = threadIdx.x;
    int wid = tid >> 5, lane = tid & 31;
    int warp_m = wid & 1, warp_n = wid >> 1;
    int m0 = blockIdx.y * 128, n0 = blockIdx.x * 128;
    const float* Ag = A + (size_t)m0 * ldA;
    const float* Wg = W + (size_t)n0 * ldW;
    int qr = lane >> 2, qc = lane & 3;

    float acc[4][4][4];
    #pragma unroll
    for (int mt = 0; mt < 4; mt++)
        #pragma unroll
        for (int nt = 0; nt < 4; nt++)
            #pragma unroll
            for (int i = 0; i < 4; i++) acc[mt][nt][i] = 0.0f;

    int KT = K / 32;
    tile_load(AsB, Ag, ldA, 0, tid);
    tile_load(WsB, Wg, ldW, 0, tid);
    asm volatile("cp.async.commit_group;");

    for (int kt = 0; kt < KT; kt++) {
        int cur = kt & 1;
        if (kt + 1 < KT) {
            tile_load(AsB + (cur ^ 1) * SBUF, Ag, ldA, (kt + 1) * 32, tid);
            tile_load(WsB + (cur ^ 1) * SBUF, Wg, ldW, (kt + 1) * 32, tid);
            asm volatile("cp.async.commit_group;");
            asm volatile("cp.async.wait_group 1;");
        } else {
            asm volatile("cp.async.wait_group 0;");
        }
        __syncthreads();
        const unsigned* Ab = (const unsigned*)(AsB + cur * SBUF);
        const unsigned* Wb = (const unsigned*)(WsB + cur * SBUF);
        #pragma unroll
        for (int ks = 0; ks < 4; ks++) {
            int k0 = ks * 8;
            unsigned af[4][4], bf[4][2];
            #pragma unroll
            for (int mt = 0; mt < 4; mt++) {
                int r = warp_m * 64 + mt * 16 + qr;
                af[mt][0] = Ab[r * SPITCH + k0 + qc];
                af[mt][1] = Ab[(r + 8) * SPITCH + k0 + qc];
                af[mt][2] = Ab[r * SPITCH + k0 + qc + 4];
                af[mt][3] = Ab[(r + 8) * SPITCH + k0 + qc + 4];
            }
            #pragma unroll
            for (int nt = 0; nt < 4; nt++) {
                int cc = warp_n * 32 + nt * 8 + qr;
                bf[nt][0] = Wb[cc * SPITCH + k0 + qc];
                bf[nt][1] = Wb[cc * SPITCH + k0 + qc + 4];
            }
            #pragma unroll
            for (int mt = 0; mt < 4; mt++)
                #pragma unroll
                for (int nt = 0; nt < 4; nt++)
                    mma_tf32(acc[mt][nt], af[mt], bf[nt]);
        }
        __syncthreads();
    }

    #pragma unroll
    for (int mt = 0; mt < 4; mt++)
        #pragma unroll
        for (int nt = 0; nt < 4; nt++) {
            int row = m0 + warp_m * 64 + mt * 16 + qr;
            int col = n0 + warp_n * 32 + nt * 8 + qc * 2;
            float* p0 = C + (size_t)row * ldC + col;
            float* p1 = C + (size_t)(row + 8) * ldC + col;
            float2 r0 = make_float2(acc[mt][nt][0], acc[mt][nt][1]);
            float2 r1 = make_float2(acc[mt][nt][2], acc[mt][nt][3]);
            if (EPI == 2) {
                // g = sigmoid(acc + gb); out = tf32r(g*o + (1-g)*v)
                float2 gbv = *(const float2*)(gb + col);
                float2 o0 = *(const float2*)(oin + (size_t)row * HID + col);
                float2 o1 = *(const float2*)(oin + (size_t)(row + 8) * HID + col);
                float2 v0 = *(const float2*)(qkvp + (size_t)row * 3072 + 2048 + col);
                float2 v1 = *(const float2*)(qkvp + (size_t)(row + 8) * 3072 + 2048 + col);
                float g00 = sigmoidf_(r0.x + gbv.x), g01 = sigmoidf_(r0.y + gbv.y);
                float g10 = sigmoidf_(r1.x + gbv.x), g11 = sigmoidf_(r1.y + gbv.y);
                r0.x = tf32r(g00 * o0.x + (1.0f - g00) * v0.x);
                r0.y = tf32r(g01 * o0.y + (1.0f - g01) * v0.y);
                r1.x = tf32r(g10 * o1.x + (1.0f - g10) * v1.x);
                r1.y = tf32r(g11 * o1.y + (1.0f - g11) * v1.y);
            } else {
                if (ROUND) {
                    r0.x = tf32r(r0.x); r0.y = tf32r(r0.y);
                    r1.x = tf32r(r1.x); r1.y = tf32r(r1.y);
                }
                if (EPI == 1) {
                    float2 o0 = *(float2*)p0, o1 = *(float2*)p1;
                    r0.x += o0.x; r0.y += o0.y; r1.x += o1.x; r1.y += o1.y;
                }
            }
            *(float2*)p0 = r0;
            *(float2*)p1 = r1;
        }
}

// ---------------- depthwise causal conv (KS=4) + bias + silu --------------
__global__ void conv_silu_kernel(const float* __restrict__ h, const float* __restrict__ cw,
                                 const float* __restrict__ cb, float* __restrict__ o) {
    size_t idx = (size_t)blockIdx.x * blockDim.x + threadIdx.x;
    int c = idx & (HID - 1);
    int t = (int)((idx >> 10) & (TT - 1));
    int b = (int)(idx >> 21);
    float acc = cb[c];
    #pragma unroll
    for (int j = 0; j < KS; j++) {
        int tt = t + j - (KS - 1);
        if (tt >= 0) acc += h[((size_t)(b * TT + tt)) * HID + c] * cw[c * KS + j];
    }
    o[idx] = tf32r(siluf_(acc));
}

// ---------------- scan pass A (elu+1 applied to k inline) ------------------
__global__ void scan_chunk_kernel(const float* __restrict__ qkv, const float* __restrict__ dp,
                                  float* __restrict__ rks, float* __restrict__ rkv,
                                  float* __restrict__ cks, float* __restrict__ ckv) {
    int c = blockIdx.x * blockDim.x + threadIdx.x;
    int j = blockIdx.y;
    int b = blockIdx.z;
    float d = sigmoidf_(dp[c >> 7]);
    float sks = 0.0f, skv = 0.0f;
    size_t base  = ((size_t)(b * TT + j * CLEN)) * 3072 + c;
    size_t obase = ((size_t)(b * TT + j * CLEN)) * HID + c;
    for (int i = 0; i < CLEN; i++) {
        float kk = elup1_(qkv[base + 1024]);
        float vv = qkv[base + 2048];
        sks = d * sks + kk;
        skv = d * skv + kk * vv;
        rks[obase] = sks;
        rkv[obase] = skv;
        base += 3072; obase += HID;
    }
    cks[(b * NCHUNK + j) * HID + c] = sks;
    ckv[(b * NCHUNK + j) * HID + c] = skv;
}

// ---------------- scan pass B ---------------------------------------------
__global__ void scan_carry_kernel(const float* __restrict__ dp,
                                  const float* __restrict__ cks, const float* __restrict__ ckv,
                                  float* __restrict__ pks, float* __restrict__ pkv) {
    int c = blockIdx.x * blockDim.x + threadIdx.x;
    int b = blockIdx.y;
    float d = sigmoidf_(dp[c >> 7]);
    float dC = expf((float)CLEN * logf(d));
    float sks = 0.0f, skv = 0.0f;
    for (int j = 0; j < NCHUNK; j++) {
        int idx = (b * NCHUNK + j) * HID + c;
        pks[idx] = sks;
        pkv[idx] = skv;
        sks = dC * sks + cks[idx];
        skv = dC * skv + ckv[idx];
    }
}

// ---------------- attn_o: elu(q)+1, carry fix, den, o (all fused) ----------
__global__ void attn_o_kernel(const float* __restrict__ qkv, const float* __restrict__ dp,
                              const float* __restrict__ rks, const float* __restrict__ rkv,
                              const float* __restrict__ pks, const float* __restrict__ pkv,
                              float* __restrict__ o) {
    int gw = (blockIdx.x * blockDim.x + threadIdx.x) >> 5;
    int lane = threadIdx.x & 31;
    int row = gw >> 3;
    int hh = gw & 7;
    int b = row >> 11;                 // 2048 rows per batch
    int t = row & (TT - 1);
    int i = t & (CLEN - 1);
    int j = t >> 7;
    float d  = sigmoidf_(dp[hh]);
    float pw = expf((float)(i + 1) * logf(d));
    size_t qbase = (size_t)row * 3072 + hh * HD;
    size_t rbase = (size_t)row * HID  + hh * HD;
    size_t pbase = (size_t)(b * NCHUNK + j) * HID + hh * HD;
    float qv[4], kvv[4], s = 0.0f;
    #pragma unroll
    for (int u = 0; u < 4; u++) {
        int dpos = lane + u * 32;
        qv[u] = elup1_(qkv[qbase + dpos]);
        float ks = rks[rbase + dpos] + pks[pbase + dpos] * pw;
        kvv[u]  = rkv[rbase + dpos] + pkv[pbase + dpos] * pw;
        s += qv[u] * ks;
    }
    #pragma unroll
    for (int k = 16; k; k >>= 1) s += __shfl_xor_sync(0xFFFFFFFFu, s, k);
    float inv = 1.0f / fmaxf(s, 1e-6f);
    #pragma unroll
    for (int u = 0; u < 4; u++) {
        int dpos = lane + u * 32;
        o[rbase + dpos] = tf32r(qv[u] * kvv[u] * inv);
    }
}

// ---------------- gmix residual + rmsnorm2 (fused, one block per row) ------
__global__ void gmix_norm_kernel(const float* __restrict__ x, const float* __restrict__ glin,
                                 const float* __restrict__ local, const float* __restrict__ attn,
                                 const float* __restrict__ w2n,
                                 float* __restrict__ x1, float* __restrict__ h2) {
    int row = blockIdx.x;
    size_t base = (size_t)row * HID;
    int tid = threadIdx.x;
    float4 xv = ((const float4*)(x + base))[tid];
    float4 gv = ((const float4*)(glin + base))[tid];
    float4 lv = ((const float4*)(local + base))[tid];
    float4 av = ((const float4*)(attn + base))[tid];
    float s0 = sigmoidf_(gv.x), s1 = sigmoidf_(gv.y);
    float s2 = sigmoidf_(gv.z), s3 = sigmoidf_(gv.w);
    float4 x1v = make_float4(xv.x + s0 * lv.x + (1.0f - s0) * av.x,
                             xv.y + s1 * lv.y + (1.0f - s1) * av.y,
                             xv.z + s2 * lv.z + (1.0f - s2) * av.z,
                             xv.w + s3 * lv.w + (1.0f - s3) * av.w);
    ((float4*)(x1 + base))[tid] = x1v;
    float ss = x1v.x * x1v.x + x1v.y * x1v.y + x1v.z * x1v.z + x1v.w * x1v.w;
    __shared__ float sred[8];
    int lane = tid & 31, wid = tid >> 5;
    #pragma unroll
    for (int k = 16; k; k >>= 1) ss += __shfl_xor_sync(0xFFFFFFFFu, ss, k);
    if (lane == 0) sred[wid] = ss;
    __syncthreads();
    if (wid == 0) {
        float t = (lane < 8) ? sred[lane] : 0.0f;
        #pragma unroll
        for (int k = 4; k; k >>= 1) t += __shfl_xor_sync(0xFFFFFFFFu, t, k);
        if (lane == 0) sred[0] = t;
    }
    __syncthreads();
    float scale = rsqrtf(sred[0] * (1.0f / (float)HID) + 1e-6f);
    float4 wv = ((const float4*)w2n)[tid];
    float4 r = make_float4(tf32r(x1v.x * scale * wv.x), tf32r(x1v.y * scale * wv.y),
                           tf32r(x1v.z * scale * wv.z), tf32r(x1v.w * scale * wv.w));
    ((float4*)(h2 + base))[tid] = r;
}

// ---------------- swiglu on fused [M, 2*INTER] buffer ----------------------
__global__ void swiglu_kernel(const float* __restrict__ ff, float* __restrict__ ffa) {
    int row = blockIdx.y;
    int n = blockIdx.x * blockDim.x + threadIdx.x;   // 0..INTER-1
    size_t ibase = (size_t)row * (2 * INTER);
    float a = ff[ibase + n];
    float b = ff[ibase + INTER + n];
    ffa[(size_t)row * INTER + n] = tf32r(siluf_(a) * b);
}

// ---------------- host side ------------------------------------------------
static inline void run_gemm(const float* A, int ldA, const float* W, int ldW,
                            float* C, int ldC, int M, int N, int K,
                            int epi, bool rnd,
                            const float* gb = nullptr, const float* oin = nullptr,
                            const float* qkvp = nullptr) {
    dim3 grid(N / 128, M / 128);
    if (epi == 2)
        tgemm_kernel<2, false><<<grid, 256, TGEMM_SMEM>>>(A, ldA, W, ldW, C, ldC, K, gb, oin, qkvp);
    else if (epi == 1)
        tgemm_kernel<1, false><<<grid, 256, TGEMM_SMEM>>>(A, ldA, W, ldW, C, ldC, K, nullptr, nullptr, nullptr);
    else if (rnd)
        tgemm_kernel<0, true ><<<grid, 256, TGEMM_SMEM>>>(A, ldA, W, ldW, C, ldC, K, nullptr, nullptr, nullptr);
    else
        tgemm_kernel<0, false><<<grid, 256, TGEMM_SMEM>>>(A, ldA, W, ldW, C, ldC, K, nullptr, nullptr, nullptr);
}

extern "C" void kernel_launch(void* const* d_in, const int* in_sizes, int n_in,
                              void* d_out, int out_size) {
    const float* x           = (const float*)d_in[0];
    const float* qkv_w       = (const float*)d_in[1];
    const float* out_proj_w  = (const float*)d_in[2];
    const float* out_gate_w  = (const float*)d_in[3];
    const float* out_gate_b  = (const float*)d_in[4];
    const float* decay_param = (const float*)d_in[5];
    const float* conv_w      = (const float*)d_in[6];
    const float* conv_b      = (const float*)d_in[7];
    const float* pw_w        = (const float*)d_in[8];
    const float* gate_w      = (const float*)d_in[9];
    const float* w1          = (const float*)d_in[10];
    const float* w2          = (const float*)d_in[11];
    const float* w3          = (const float*)d_in[12];
    const float* norm1_w     = (const float*)d_in[13];
    const float* norm2_w     = (const float*)d_in[14];
    float* out = (float*)d_out;

    static int smem_set = 0;
    if (!smem_set) {
        cudaFuncSetAttribute(tgemm_kernel<0, false>,
                             cudaFuncAttributeMaxDynamicSharedMemorySize, (int)TGEMM_SMEM);
        cudaFuncSetAttribute(tgemm_kernel<0, true>,
                             cudaFuncAttributeMaxDynamicSharedMemorySize, (int)TGEMM_SMEM);
        cudaFuncSetAttribute(tgemm_kernel<1, false>,
                             cudaFuncAttributeMaxDynamicSharedMemorySize, (int)TGEMM_SMEM);
        cudaFuncSetAttribute(tgemm_kernel<2, false>,
                             cudaFuncAttributeMaxDynamicSharedMemorySize, (int)TGEMM_SMEM);
        smem_set = 1;
    }

    float* S = nullptr;
    cudaGetSymbolAddress((void**)&S, g_scratch);

    float* g_h    = S + OFF_H;
    float* g_qkv  = S + OFF_QKV;
    float* g_conv = S + OFF_CONV;
    float* g_loc  = S + OFF_LOCAL;
    float* g_rks  = S + OFF_RKS;
    float* g_rkv  = S + OFF_RKV;
    float* g_o    = S + OFF_O;
    float* g_tmp  = S + OFF_TMP;
    float* g_o2   = S + OFF_O2;
    float* g_attn = S + OFF_ATTN;
    float* g_x1   = S + OFF_X1;
    float* g_h2   = S + OFF_H2;
    float* g_ff   = S + OFF_FF;
    float* g_ffa  = S + OFF_FFA;
    float* g_cks  = S + OFF_CKS;
    float* g_ckv  = S + OFF_CKV;
    float* g_pks  = S + OFF_PKS;
    float* g_pkv  = S + OFF_PKV;
    float* c_qkvw = S + OFF_WQKV;
    float* c_opw  = S + OFF_WOP;
    float* c_ogw  = S + OFF_WOG;
    float* c_pww  = S + OFF_WPW;
    float* c_gtw  = S + OFF_WGT;
    float* c_w1   = S + OFF_WW1;     // c_w1..c_w2 contiguous: [2*INTER, HID]
    float* c_w2   = S + OFF_WW2;
    float* c_w3   = S + OFF_WW3;

    const int NEH = 256;
    const int GMH = (int)(SZ_MH / NEH);

    // 0. round weights to tf32 once per launch
    cvt_tf32_kernel<<<(3 * HID * HID) / 256, 256>>>(qkv_w, c_qkvw, 3 * HID * HID);
    cvt_tf32_kernel<<<(HID * HID) / 256, 256>>>(out_proj_w, c_opw, HID * HID);
    cvt_tf32_kernel<<<(HID * HID) / 256, 256>>>(out_gate_w, c_ogw, HID * HID);
    cvt_tf32_kernel<<<(HID * HID) / 256, 256>>>(pw_w, c_pww, HID * HID);
    cvt_tf32_kernel<<<(2 * HID * HID) / 256, 256>>>(gate_w, c_gtw, 2 * HID * HID);
    cvt_tf32_kernel<<<(INTER * HID) / 256, 256>>>(w1, c_w1, INTER * HID);
    cvt_tf32_kernel<<<(INTER * HID) / 256, 256>>>(w2, c_w2, INTER * HID);
    cvt_tf32_kernel<<<(INTER * HID) / 256, 256>>>(w3, c_w3, INTER * HID);

    // 1. h = rmsnorm(x, norm1_w)
    rmsnorm_kernel<<<MROWS, 256>>>(x, norm1_w, g_h);

    // 2. qkv = h @ qkv_w^T
    run_gemm(g_h, HID, c_qkvw, HID, g_qkv, 3 * HID, MROWS, 3 * HID, HID, 0, false);

    // 3. conv branch
    conv_silu_kernel<<<GMH, NEH>>>(g_h, conv_w, conv_b, g_conv);
    run_gemm(g_conv, HID, c_pww, HID, g_loc, HID, MROWS, HID, HID, 0, true);

    // 4. decayed scans (elu folded into scan; fix folded into attn_o)
    {
        dim3 gA(HID / 256, NCHUNK, BB);
        scan_chunk_kernel<<<gA, 256>>>(g_qkv, decay_param, g_rks, g_rkv, g_cks, g_ckv);
        dim3 gB(HID / 256, BB);
        scan_carry_kernel<<<gB, 256>>>(decay_param, g_cks, g_ckv, g_pks, g_pkv);
    }

    // 5. o = elu(q)+1 * (rkv + carry) / den   (fused)
    attn_o_kernel<<<MROWS * NH * 32 / 256, 256>>>(g_qkv, decay_param,
                                                  g_rks, g_rkv, g_pks, g_pkv, g_o);

    // 6. out gate GEMM with fused mix epilogue -> o2
    run_gemm(g_o, HID, c_ogw, HID, g_o2, HID, MROWS, HID, HID, 2, false,
             out_gate_b, g_o, g_qkv);

    // 7. attn = o2 @ out_proj^T (rounded)
    run_gemm(g_o2, HID, c_opw, HID, g_attn, HID, MROWS, HID, HID, 0, true);

    // 8. gmix (split-K over concat) + fused residual + rmsnorm2
    run_gemm(g_loc,  HID, c_gtw,       2 * HID, g_tmp, HID, MROWS, HID, HID, 0, false);
    run_gemm(g_attn, HID, c_gtw + HID, 2 * HID, g_tmp, HID, MROWS, HID, HID, 1, false);
    gmix_norm_kernel<<<MROWS, 256>>>(x, g_tmp, g_loc, g_attn, norm2_w, g_x1, g_h2);

    // 9. FFN: fused w1|w2 GEMM (N=5632), swiglu, then w3 accumulated onto x1
    run_gemm(g_h2, HID, c_w1, HID, g_ff, 2 * INTER, MROWS, 2 * INTER, HID, 0, false);
    {
        dim3 gs(INTER / 256, MROWS);
        swiglu_kernel<<<gs, 256>>>(g_ff, g_ffa);
    }
    cudaMemcpyAsync(out, g_x1, SZ_MH * sizeof(float), cudaMemcpyDeviceToDevice);
    run_gemm(g_ffa, INTER, c_w3, INTER, out, HID, MROWS, HID, INTER, 1, false);
}